// round 17
// baseline (speedup 1.0000x reference)
#include <cuda_runtime.h>
#include <cuda_bf16.h>

// Shapes: A=1, B=8, M=256, H(=Kdim)=2048, E=8, K=2, N=2048
// out (scalar) = sum_{b,e,k} sp[b,e] * hsum[b,k] * wsum[e,k]
//   hsum[b,k] = sum_m hidden[0,b,m,k]     (16 MB stream)
//   wsum[e,k] = sum_n W[0,e,k,n]          (134 MB stream)
//
// Fully fused single kernel, all prior failure modes engineered out:
//   bids 0..511    : hidden 32KB units (HALF a W unit -> finish first at fair
//                    BW share; all wave-1 resident -> no deadlock), fold into
//                    g_hsum via spread RED.F32, release-signal g_hdone.
//   bids 512..2559 : W row sums (one warp per (e,k) row, 64KB/block). After
//                    streaming, poll g_hdone (first try succeeds; nanosleep
//                    backoff), read 8 hsum values + sp, per-warp partial,
//                    block-reduce, PLAIN store to g_slots[block].
//   ticket         : hierarchical (32 x 80 -> 1 x 32) release atomics -> no
//                    same-address serialization. Last block: one fence, sums
//                    2048 slots, writes out, re-zeroes ALL state for replay.

#define Bd 8
#define Md 256
#define Hd 2048
#define Ed 8
#define Nd 2048

#define H_BLOCKS 512               // 32 KB each: (b, 4 m-rows)
#define W_BLOCKS 2048              // 64 KB each: 8 W rows
#define GRID     (H_BLOCKS + W_BLOCKS)
#define NT1      32
#define QUOTA    (GRID / NT1)      // 80

__device__ float        g_hsum[Bd * Hd];     // zero at entry; re-zeroed by tail
__device__ double       g_slots[W_BLOCKS];   // plain stores, rewritten each run
__device__ unsigned int g_hdone;             // re-zeroed by tail
__device__ unsigned int g_t1[NT1];           // re-zeroed by tail
__device__ unsigned int g_t2;                // re-zeroed by tail

__device__ __forceinline__ unsigned int ld_acq(const unsigned int* p) {
    unsigned int v;
    asm volatile("ld.acquire.gpu.global.u32 %0, [%1];" : "=r"(v) : "l"(p) : "memory");
    return v;
}
__device__ __forceinline__ unsigned int atom_rel_add(unsigned int* p, unsigned int v) {
    unsigned int r;
    asm volatile("atom.release.gpu.global.add.u32 %0, [%1], %2;"
                 : "=r"(r) : "l"(p), "r"(v) : "memory");
    return r;
}

__global__ void __launch_bounds__(256) k_all(const float* __restrict__ W,
                                             const float* __restrict__ hidden,
                                             const float* __restrict__ sp,
                                             float* __restrict__ out) {
    __shared__ double s_red[8];
    __shared__ unsigned int s_last;
    const int tid  = threadIdx.x;
    const int warp = tid >> 5;
    const int lane = tid & 31;

    if (blockIdx.x < H_BLOCKS) {
        // ---------- hidden: 32KB unit = (b, 4 m-rows), fold via spread REDs ----------
        int b  = blockIdx.x >> 6;                    // 0..7
        int m0 = (blockIdx.x & 63) * 4;              // 4 rows
        const float4* base = reinterpret_cast<const float4*>(
            hidden + (size_t)(b * Md + m0) * Hd);
#pragma unroll
        for (int j = 0; j < 2; j++) {
            int k4 = tid + j * 256;                  // 0..511
            float4 acc = make_float4(0.f, 0.f, 0.f, 0.f);
#pragma unroll
            for (int r = 0; r < 4; r++) {
                float4 v = base[r * (Hd / 4) + k4];
                acc.x += v.x; acc.y += v.y; acc.z += v.z; acc.w += v.w;
            }
            float* dst = &g_hsum[b * Hd + k4 * 4];
            atomicAdd(dst + 0, acc.x);               // spread RED.F32, no return
            atomicAdd(dst + 1, acc.y);
            atomicAdd(dst + 2, acc.z);
            atomicAdd(dst + 3, acc.w);
        }
        __syncthreads();
        if (tid == 0) atom_rel_add(&g_hdone, 1u);    // REDs visible before signal
    } else {
        // ---------- W: one warp per row, then fused tail ----------
        int u   = blockIdx.x - H_BLOCKS;             // 0..2047
        int row = u * 8 + warp;                      // e*2048 + k
        int e   = row >> 11;
        int k   = row & 2047;

        const float4* src = reinterpret_cast<const float4*>(W + (size_t)row * Nd);
        float s = 0.f;
#pragma unroll
        for (int i = 0; i < 16; i++) {               // 16 f4 * 32 lanes = 2048
            float4 v = src[lane + 32 * i];
            s += (v.x + v.y) + (v.z + v.w);
        }
#pragma unroll
        for (int o = 16; o > 0; o >>= 1)
            s += __shfl_xor_sync(0xffffffff, s, o);

        // hidden units are half-size and launch first -> normally already done
        while (ld_acq(&g_hdone) < H_BLOCKS) __nanosleep(200);

        // partial = sum_b sp[b,e] * hsum[b,k]  (lanes 0..7, coalesced-ish 8 sectors)
        float v = 0.f;
        if (lane < Bd)
            v = __ldcg(&g_hsum[lane * Hd + k]) * sp[lane * 16 + e];
#pragma unroll
        for (int o = 4; o > 0; o >>= 1)
            v += __shfl_xor_sync(0xffffffff, v, o);  // sums lanes 0..7 (rest are 0)

        if (lane == 0) s_red[warp] = (double)s * (double)v;
        __syncthreads();
        if (warp == 0) {
            double d = (lane < 8) ? s_red[lane] : 0.0;
#pragma unroll
            for (int o = 4; o > 0; o >>= 1)
                d += __shfl_xor_sync(0xffffffff, d, o);
            if (lane == 0) g_slots[u] = d;           // plain store, distinct addr
        }
    }

    // ---------- hierarchical ticket: 32 x 80 -> 1 x 32 ----------
    __syncthreads();
    if (tid == 0) {
        s_last = 0u;
        unsigned int t1 = atom_rel_add(&g_t1[blockIdx.x & (NT1 - 1)], 1u);
        if (t1 == QUOTA - 1) {
            unsigned int t2 = atom_rel_add(&g_t2, 1u);
            if (t2 == NT1 - 1) s_last = 1u;
        }
    }
    __syncthreads();

    if (s_last) {
        asm volatile("fence.acq_rel.gpu;" ::: "memory");   // one-time, drained chip
        // sum the 2048 slots
        double d = 0.0;
#pragma unroll
        for (int i = 0; i < W_BLOCKS / 256; i++)
            d += g_slots[i * 256 + tid];
#pragma unroll
        for (int o = 16; o > 0; o >>= 1)
            d += __shfl_xor_sync(0xffffffff, d, o);
        if (lane == 0) s_red[warp] = d;
        __syncthreads();
        if (warp == 0) {
            double t = (lane < 8) ? s_red[lane] : 0.0;
#pragma unroll
            for (int o = 4; o > 0; o >>= 1)
                t += __shfl_xor_sync(0xffffffff, t, o);
            if (lane == 0) out[0] = (float)t;
        }
        // re-zero ALL state for the next graph replay
        for (int i = tid; i < Bd * Hd; i += 256) g_hsum[i] = 0.f;
        if (tid < NT1) g_t1[tid] = 0u;
        if (tid == 0) { g_t2 = 0u; g_hdone = 0u; }
    }
}

extern "C" void kernel_launch(void* const* d_in, const int* in_sizes, int n_in,
                              void* d_out, int out_size) {
    const float* hidden = (const float*)d_in[0];   // (1,8,256,2048)
    const float* sp     = (const float*)d_in[1];   // (1,8,2,8)
    const float* W      = (const float*)d_in[2];   // (1,8,2048,2048)
    float* out = (float*)d_out;

    k_all<<<GRID, 256>>>(W, hidden, sp, out);
}